// round 16
// baseline (speedup 1.0000x reference)
#include <cuda_runtime.h>
#include <math.h>

#define BATCH 64
#define SEQ   512
#define EMBED 256
#define HID   512
#define GD    768     // HID + EMBED
#define NCLS  4

#define NBLK  128     // 2 batch halves x 64 column groups
#define NTHR  256     // 8 warps
#define BG    32      // batch rows per CTA
#define ND    32      // dot-columns per CTA
#define K4T   192     // GD / 4
#define HALF_CTAS 64

// SMEM: w[32][768] + inp[32][768] (XOR-swizzled) + 8 partial sets + bias
#define SM_W       0
#define SM_INP     (32*768)
#define SM_PART    (SM_INP + 32*768)
#define SET_STRIDE 1056                 // 32 cols' x 33 (row-padded)
#define SM_BIAS    (SM_PART + 8*SET_STRIDE)
#define SMEM_FLOATS (SM_BIAS + 32)
#define SMEM_BYTES  (SMEM_FLOATS * 4)   // 230,528 B

__device__ float g_h[2][BATCH*HID];
__device__ float g_maxh[BATCH*HID];
__device__ unsigned long long g_cnt;          // full-grid ticket counter
__device__ unsigned long long g_half[64];     // per-half counters (slots 0, 32)

__device__ __forceinline__ float sigf(float x)     { return 1.0f / (1.0f + __expf(-x)); }
__device__ __forceinline__ float tanhfast(float x) { return 2.0f / (1.0f + __expf(-2.0f*x)) - 1.0f; }

__device__ __forceinline__ void fma2(unsigned long long &d,
                                     unsigned long long a, unsigned long long b) {
    asm("fma.rn.f32x2 %0, %1, %2, %0;" : "+l"(d) : "l"(a), "l"(b));
}
__device__ __forceinline__ float sum2(unsigned long long v) {
    float lo, hi;
    asm("mov.b64 {%0,%1}, %2;" : "=f"(lo), "=f"(hi) : "l"(v));
    return lo + hi;
}

// cp.async 16B, L2-only (.cg): required for h (cross-SM coherence), fine for emb
__device__ __forceinline__ void cp16_cg(unsigned int saddr, const void* g) {
    asm volatile("cp.async.cg.shared.global [%0], [%1], 16;" :: "r"(saddr), "l"(g));
}
#define CP_COMMIT()  asm volatile("cp.async.commit_group;" ::: "memory")
#define CP_WAITALL() asm volatile("cp.async.wait_all;"     ::: "memory")

// Full-grid ticket barrier (fence-free; init and finish only).
__device__ __forceinline__ void ticket_barrier() {
    __syncthreads();
    if (threadIdx.x == 0) {
        unsigned long long ticket;
        asm volatile("atom.release.gpu.add.u64 %0, [%1], %2;"
                     : "=l"(ticket) : "l"(&g_cnt), "l"(1ULL) : "memory");
        unsigned long long target = (ticket / NBLK + 1ULL) * (unsigned long long)NBLK;
        unsigned long long cur;
        do {
            asm volatile("ld.acquire.gpu.u64 %0, [%1];"
                         : "=l"(cur) : "l"(&g_cnt) : "memory");
        } while (cur < target);
    }
    __syncthreads();
}

__device__ __forceinline__ void loadx(ulonglong2 xv[4], const float* xr0, int k4, int rg) {
    int ox = ((k4 ^ rg) << 2);
    #pragma unroll
    for (int r = 0; r < 4; r++)
        xv[r] = *(const ulonglong2*)(xr0 + r*GD + ox);
}

__device__ __forceinline__ void gemm_step(unsigned long long acc[4][8],
                                          const ulonglong2 xv[4],
                                          const float* wc0, int o0, int o1) {
    #pragma unroll
    for (int c = 0; c < 8; c++) {
        ulonglong2 wv = *(const ulonglong2*)(wc0 + c*GD + (c < 4 ? o0 : o1));
        #pragma unroll
        for (int r = 0; r < 4; r++) {
            fma2(acc[r][c], xv[r].x, wv.x);
            fma2(acc[r][c], xv[r].y, wv.y);
        }
    }
}

extern "C" __global__ void __launch_bounds__(NTHR, 1)
lstm_persistent(const int*   __restrict__ ids,
                const float* __restrict__ emb,
                const float* __restrict__ Wf, const float* __restrict__ bf,
                const float* __restrict__ Wi, const float* __restrict__ bi,
                const float* __restrict__ Wo, const float* __restrict__ bo,
                const float* __restrict__ Wc, const float* __restrict__ bc,
                const float* __restrict__ fcw, const float* __restrict__ fcb,
                float* __restrict__ out)
{
    extern __shared__ float sm[];
    float* w_s    = sm + SM_W;
    float* inp_s  = sm + SM_INP;
    float* part_s = sm + SM_PART;
    float* bias_s = sm + SM_BIAS;

    const int tid  = threadIdx.x;
    const int cta  = blockIdx.x;
    const int half = cta & 1;
    const int b0   = half * BG;
    const int j0   = (cta >> 1) * 8;
    const int wid  = tid >> 5;               // 0..7
    const int lane = tid & 31;

    unsigned long long* hctr = &g_half[half * 32];

    const float* Wg[4]  = {Wf, Wi, Wo, Wc};
    const float* bgp[4] = {bf, bi, bo, bc};

    // ---- one-time: weight slice into swizzled SMEM (key (d>>2)&7) ----
    for (int idx = tid; idx < ND*K4T; idx += NTHR) {
        int d  = idx / K4T;
        int k4 = idx - d*K4T;
        int g  = d >> 3, jj = d & 7;
        float4 v = ((const float4*)(Wg[g] + (size_t)(j0 + jj) * GD))[k4];
        *(float4*)(w_s + d*GD + ((k4 ^ ((d >> 2) & 7)) << 2)) = v;
    }
    if (tid < ND) {
        int g = tid >> 3, jj = tid & 7;
        bias_s[tid] = bgp[g][j0 + jj];
    }
    if (tid < BG*8) {                        // zero h(0) region this CTA owns
        int r = tid >> 3, jj = tid & 7;
        g_h[0][(b0 + r)*HID + j0 + jj] = 0.0f;
    }

    // GEMM mapping (R6 exact): lane tile 4 rows x 8 cols, warp K-segment 24 k4
    const int rg = lane >> 2;                // rows 4rg..4rg+3 (x key = rg)
    const int cg = lane & 3;                 // cols 8cg..8cg+7
    const int kb = wid * 24;                 // [24w, 24w+24)
    const int s0 = 2*cg;                     // w key, cols 8cg..8cg+3
    const int s1 = 2*cg + 1;                 // w key, cols 8cg+4..8cg+7
    const float* xr0 = inp_s + (4*rg) * GD;
    const float* wc0 = w_s   + (8*cg) * GD;

    // warp-private staging: lane stages ONE row x the warp's 24 k4
    // row permutation keeps each store phase on 8 distinct bank groups
    const int srow = ((lane & 7) << 2) | (lane >> 3);   // 0..31 bijection
    const int skey = srow >> 2;
    const unsigned int sdst_s =
        (unsigned int)__cvta_generic_to_shared(inp_s + srow * GD);
    const bool reads_h   = (kb < 128);        // warps 0..5
    const bool reads_emb = (kb + 23 >= 128);  // warps 5..7
    const int* idrow = ids + (b0 + srow)*SEQ;

    // epilogue mapping: one thread per (batch row, hidden unit)
    const int eb  = tid >> 3;                 // 0..31
    const int ejj = tid & 7;                  // 0..7

    float cst  = 0.0f;
    float mmax = -INFINITY;

    // ---- prologue: stage emb(0) part of own K-range (warps 5..7) ----
    if (reads_emb) {
        int id0 = __ldg(idrow + 0);
        const float4* erow = (const float4*)(emb + (size_t)id0 * EMBED);
        #pragma unroll
        for (int kk = 0; kk < 24; kk++) {
            int k4 = kb + kk;
            if (k4 >= 128)
                cp16_cg(sdst_s + ((k4 ^ skey) << 4), erow + (k4 - 128));
        }
        CP_COMMIT();
    }

    unsigned long long hbase = *((volatile unsigned long long*)hctr);

    ticket_barrier();                          // h(0), hbase settled grid-wide

    for (int t = 0; t < SEQ; t++) {
        // ---- 1. warp-private: release + stage own h K-range ----
        if (reads_h) {
            if (t > 0) {
                if (lane == 0) {
                    unsigned long long target =
                        hbase + (unsigned long long)HALF_CTAS * t;
                    unsigned long long cur;
                    do {
                        asm volatile("ld.acquire.gpu.u64 %0, [%1];"
                                     : "=l"(cur) : "l"(hctr) : "memory");
                    } while (cur < target);
                }
                __syncwarp();
            }
            const float4* hrow =
                (const float4*)(g_h[t & 1] + (size_t)(b0 + srow) * HID);
            #pragma unroll
            for (int kk = 0; kk < 24; kk++) {
                int k4 = kb + kk;
                if (k4 < 128)
                    cp16_cg(sdst_s + ((k4 ^ skey) << 4), hrow + k4);
            }
            CP_COMMIT();
        }
        CP_WAITALL();                          // own h + own emb (prefetched)
        __syncwarp();

        // ---- 2. GEMM over own 24 k4 (R6 double-buffered body) ----
        unsigned long long acc[4][8];
        #pragma unroll
        for (int r = 0; r < 4; r++)
            #pragma unroll
            for (int c = 0; c < 8; c++) acc[r][c] = 0ULL;
        {
            ulonglong2 xa[4], xb[4];
            loadx(xa, xr0, kb, rg);
            #pragma unroll 2
            for (int kk = 0; kk < 24; kk += 2) {
                loadx(xb, xr0, kb + kk + 1, rg);
                gemm_step(acc, xa, wc0, ((kb+kk)   ^ s0) << 2, ((kb+kk)   ^ s1) << 2);
                if (kk + 2 < 24) loadx(xa, xr0, kb + kk + 2, rg);
                gemm_step(acc, xb, wc0, ((kb+kk+1) ^ s0) << 2, ((kb+kk+1) ^ s1) << 2);
            }
        }

        // ---- 3. emb(t+1) prefetch into own (already consumed) region ----
        if (reads_emb && t + 1 < SEQ) {
            int id1 = __ldg(idrow + t + 1);
            const float4* erow = (const float4*)(emb + (size_t)id1 * EMBED);
            #pragma unroll
            for (int kk = 0; kk < 24; kk++) {
                int k4 = kb + kk;
                if (k4 >= 128)
                    cp16_cg(sdst_s + ((k4 ^ skey) << 4), erow + (k4 - 128));
            }
            CP_COMMIT();
        }

        // ---- 4. partial store (scalar, conflict-free 33-stride) ----
        {
            float* myset = part_s + wid*SET_STRIDE;
            #pragma unroll
            for (int c = 0; c < 8; c++)
                #pragma unroll
                for (int r = 0; r < 4; r++)
                    myset[(4*c + cg)*33 + 4*rg + r] = sum2(acc[r][c]);
        }
        __syncthreads();                       // all 8 sets written

        // ---- 5. epilogue: sum 8 segments, gates, state update, h store ----
        {
            float pf = bias_s[ 0 + ejj];
            float pi = bias_s[ 8 + ejj];
            float po = bias_s[16 + ejj];
            float pg = bias_s[24 + ejj];
            #pragma unroll
            for (int s = 0; s < 8; s++) {
                const float* sp = part_s + s*SET_STRIDE + eb;
                pf += sp[(4*ejj + 0)*33];
                pi += sp[(4*ejj + 1)*33];
                po += sp[(4*ejj + 2)*33];
                pg += sp[(4*ejj + 3)*33];
            }
            float f  = sigf(pf);
            float iv = sigf(pi);
            float o  = sigf(po);
            float gg = tanhfast(pg);
            cst = f*cst + iv*gg;
            float h = o * tanhfast(cst);
            mmax = fmaxf(mmax, h);
            g_h[(t + 1) & 1][(size_t)(b0 + eb)*HID + j0 + ejj] = h;
        }
        __syncthreads();                       // h stores + partial reads done

        // ---- 6. publish h(t+1) ----
        if (tid == 0 && t + 1 < SEQ)
            asm volatile("red.release.gpu.add.u64 [%0], %1;"
                         :: "l"(hctr), "l"(1ULL) : "memory");
    }

    // ---- max-over-time out, then tiny FC on CTA 0 ----
    g_maxh[(size_t)(b0 + eb)*HID + j0 + ejj] = mmax;
    ticket_barrier();

    if (cta == 0) {
        int b  = tid >> 2;
        int ci = tid & 3;
        const float4* a4 = (const float4*)(g_maxh + (size_t)b * HID);
        const float4* w4 = (const float4*)(fcw + (size_t)ci * HID);
        float acc0 = fcb[ci];
        #pragma unroll 4
        for (int k = 0; k < HID/4; k++) {
            float4 a = __ldcg(a4 + k);
            float4 w = w4[k];
            acc0 += a.x*w.x + a.y*w.y + a.z*w.z + a.w*w.w;
        }
        out[b*NCLS + ci] = acc0;
    }
}

extern "C" void kernel_launch(void* const* d_in, const int* in_sizes, int n_in,
                              void* d_out, int out_size)
{
    const int*   ids = (const int*)  d_in[0];
    const float* emb = (const float*)d_in[1];
    const float* Wf  = (const float*)d_in[2];
    const float* bf  = (const float*)d_in[3];
    const float* Wi  = (const float*)d_in[4];
    const float* bi  = (const float*)d_in[5];
    const float* Wo  = (const float*)d_in[6];
    const float* bo  = (const float*)d_in[7];
    const float* Wc  = (const float*)d_in[8];
    const float* bc  = (const float*)d_in[9];
    const float* fcw = (const float*)d_in[10];
    const float* fcb = (const float*)d_in[11];
    float* out = (float*)d_out;

    cudaFuncSetAttribute(lstm_persistent,
                         cudaFuncAttributeMaxDynamicSharedMemorySize, SMEM_BYTES);
    lstm_persistent<<<NBLK, NTHR, SMEM_BYTES>>>(ids, emb, Wf, bf, Wi, bi,
                                                Wo, bo, Wc, bc, fcw, fcb, out);
}

// round 17
// speedup vs baseline: 1.3820x; 1.3820x over previous
#include <cuda_runtime.h>
#include <math.h>

#define BATCH 64
#define SEQ   512
#define EMBED 256
#define HID   512
#define GD    768     // HID + EMBED
#define NCLS  4

#define NBLK  128     // 2 batch halves x 64 column groups
#define NTHR  256     // 8 warps
#define BG    32      // batch rows per CTA
#define ND    32      // dot-columns per CTA = 4 gates * 8 hidden units
#define K4T   192     // GD / 4 (float4 count per row)
#define CTAS_PER_CTR 8   // 64 CTAs per half / 8 counters

// SMEM: w[32][768] + inp[32][768] (XOR-swizzled) + 8 partial sets + bias
#define SM_W       0
#define SM_INP     (32*768)
#define SM_PART    (SM_INP + 32*768)
#define SET_STRIDE 1056                 // 32 cols' x 33 (row-padded)
#define SM_BIAS    (SM_PART + 8*SET_STRIDE)
#define SMEM_FLOATS (SM_BIAS + 32)
#define SMEM_BYTES  (SMEM_FLOATS * 4)   // 230,528 B

__device__ float g_h[2][BATCH*HID];
__device__ float g_maxh[BATCH*HID];
__device__ unsigned long long g_cnt;            // full-grid ticket counter
// 2 halves x 8 distributed counters, 256B apart (separate LTS slices)
__device__ unsigned long long g_bar2[2*8*32];

__device__ __forceinline__ float sigf(float x)     { return 1.0f / (1.0f + __expf(-x)); }
__device__ __forceinline__ float tanhfast(float x) { return 2.0f / (1.0f + __expf(-2.0f*x)) - 1.0f; }

__device__ __forceinline__ void fma2(unsigned long long &d,
                                     unsigned long long a, unsigned long long b) {
    asm("fma.rn.f32x2 %0, %1, %2, %0;" : "+l"(d) : "l"(a), "l"(b));
}
__device__ __forceinline__ float sum2(unsigned long long v) {
    float lo, hi;
    asm("mov.b64 {%0,%1}, %2;" : "=f"(lo), "=f"(hi) : "l"(v));
    return lo + hi;
}

// cp.async 16B, L2-only (.cg): required for h (cross-SM coherence), fine for emb
__device__ __forceinline__ void cp16_cg(unsigned int saddr, const void* g) {
    asm volatile("cp.async.cg.shared.global [%0], [%1], 16;" :: "r"(saddr), "l"(g));
}
#define CP_COMMIT()  asm volatile("cp.async.commit_group;" ::: "memory")
#define CP_WAITALL() asm volatile("cp.async.wait_all;"     ::: "memory")

// Full-grid ticket barrier (fence-free; init and finish only).
__device__ __forceinline__ void ticket_barrier() {
    __syncthreads();
    if (threadIdx.x == 0) {
        unsigned long long ticket;
        asm volatile("atom.release.gpu.add.u64 %0, [%1], %2;"
                     : "=l"(ticket) : "l"(&g_cnt), "l"(1ULL) : "memory");
        unsigned long long target = (ticket / NBLK + 1ULL) * (unsigned long long)NBLK;
        unsigned long long cur;
        do {
            asm volatile("ld.acquire.gpu.u64 %0, [%1];"
                         : "=l"(cur) : "l"(&g_cnt) : "memory");
        } while (cur < target);
    }
    __syncthreads();
}

__device__ __forceinline__ void loadx(ulonglong2 xv[4], const float* xr0, int k4, int rg) {
    int ox = ((k4 ^ rg) << 2);
    #pragma unroll
    for (int r = 0; r < 4; r++)
        xv[r] = *(const ulonglong2*)(xr0 + r*GD + ox);
}

__device__ __forceinline__ void gemm_step(unsigned long long acc[4][8],
                                          const ulonglong2 xv[4],
                                          const float* wc0, int o0, int o1) {
    #pragma unroll
    for (int c = 0; c < 8; c++) {
        ulonglong2 wv = *(const ulonglong2*)(wc0 + c*GD + (c < 4 ? o0 : o1));
        #pragma unroll
        for (int r = 0; r < 4; r++) {
            fma2(acc[r][c], xv[r].x, wv.x);
            fma2(acc[r][c], xv[r].y, wv.y);
        }
    }
}

extern "C" __global__ void __launch_bounds__(NTHR, 1)
lstm_persistent(const int*   __restrict__ ids,
                const float* __restrict__ emb,
                const float* __restrict__ Wf, const float* __restrict__ bf,
                const float* __restrict__ Wi, const float* __restrict__ bi,
                const float* __restrict__ Wo, const float* __restrict__ bo,
                const float* __restrict__ Wc, const float* __restrict__ bc,
                const float* __restrict__ fcw, const float* __restrict__ fcb,
                float* __restrict__ out)
{
    extern __shared__ float sm[];
    float* w_s    = sm + SM_W;
    float* inp_s  = sm + SM_INP;
    float* part_s = sm + SM_PART;
    float* bias_s = sm + SM_BIAS;

    const int tid  = threadIdx.x;
    const int cta  = blockIdx.x;
    const int half = cta & 1;
    const int b0   = half * BG;             // batch half
    const int j0   = (cta >> 1) * 8;        // hidden-unit group (8 units)
    const int wid  = tid >> 5;              // 0..7
    const int lane = tid & 31;

    // distributed barrier: this CTA arrives at counter ((cta>>1)&7) of its half
    unsigned long long* myctr =
        &g_bar2[(half*8 + ((cta >> 1) & 7)) * 32];
    // each lane<8 polls one counter of this half
    unsigned long long* pollctr =
        &g_bar2[(half*8 + (lane & 7)) * 32];

    const float* Wg[4]  = {Wf, Wi, Wo, Wc};
    const float* bgp[4] = {bf, bi, bo, bc};

    // ---- one-time: weight slice into swizzled SMEM (key (d>>2)&7) ----
    for (int idx = tid; idx < ND*K4T; idx += NTHR) {
        int d  = idx / K4T;
        int k4 = idx - d*K4T;
        int g  = d >> 3, jj = d & 7;
        float4 v = ((const float4*)(Wg[g] + (size_t)(j0 + jj) * GD))[k4];
        *(float4*)(w_s + d*GD + ((k4 ^ ((d >> 2) & 7)) << 2)) = v;
    }
    if (tid < ND) {
        int g = tid >> 3, jj = tid & 7;
        bias_s[tid] = bgp[g][j0 + jj];
    }
    // zero the h(0) region this CTA owns
    if (tid < BG*8) {
        int r = tid >> 3, jj = tid & 7;
        g_h[0][(b0 + r)*HID + j0 + jj] = 0.0f;
    }

    // GEMM mapping: 8 warps, lane tile 4 rows x 8 cols (R6 exact)
    const int rg = lane >> 2;               // rows 4rg..4rg+3 (x key = rg)
    const int cg = lane & 3;                // cols 8cg..8cg+7
    const int kb = wid * 24;                // 8-way split-K segment base
    const int s0 = (2*cg) & 7;
    const int s1 = (2*cg + 1) & 7;
    const float* xr0 = inp_s + (4*rg) * GD;
    const float* wc0 = w_s   + (8*cg) * GD;

    // staging mapping (R6 exact): warp owns 4 rows stride 4
    const int dr    = lane >> 3;             // 0..3
    const int dk    = lane & 7;              // 0..7
    const int rbase = (wid & 3) + (wid >> 2) * 16;
    const int srow_ = rbase + 4*dr;
    const int ssw   = srow_ >> 2;
    float* sdst = inp_s + srow_ * GD;
    const unsigned int sdst_s = (unsigned int)__cvta_generic_to_shared(sdst);
    const int* idrow = ids + (b0 + srow_)*SEQ;

    // epilogue mapping: one thread per (batch row, hidden unit)
    const int eb  = tid >> 3;                // 0..31
    const int ejj = tid & 7;                 // 0..7

    float cst  = 0.0f;
    float mmax = -INFINITY;

    // ---- pre-stage embedding for t=0 ----
    {
        int id0 = __ldg(idrow + 0);
        const float4* erow = (const float4*)(emb + (size_t)id0 * EMBED);
        #pragma unroll
        for (int o = 0; o < 8; o++) {
            int k4 = (16 + o)*8 + dk;
            *(float4*)(sdst + ((k4 ^ ssw) << 2)) = erow[o*8 + dk];
        }
    }

    // per-replay base snapshot of this lane's poll counter (monotonic counters;
    // no arrivals can occur until every CTA passes the ticket barrier below)
    unsigned long long pbase = *((volatile unsigned long long*)pollctr);

    ticket_barrier();                         // h(0), emb(0), bases settled

    for (int t = 0; t < SEQ; t++) {
        // ---- 1. stage h(t) via cp.async (.cg = L2-direct) ----
        {
            const float4* hrow = (const float4*)(g_h[t & 1] + (size_t)(b0 + srow_) * HID);
            #pragma unroll
            for (int oct = 0; oct < 16; oct++) {
                int k4 = oct*8 + dk;
                cp16_cg(sdst_s + ((k4 ^ ssw) << 4), hrow + k4);
            }
            CP_COMMIT();
        }
        CP_WAITALL();                         // h(this step) + emb(last step)
        __syncthreads();

        // ---- 2. register-tiled split-K GEMM with x prefetch (R6 exact) ----
        unsigned long long acc[4][8];
        #pragma unroll
        for (int r = 0; r < 4; r++)
            #pragma unroll
            for (int c = 0; c < 8; c++) acc[r][c] = 0ULL;

        {
            ulonglong2 xa[4], xb[4];
            loadx(xa, xr0, kb, rg);
            #pragma unroll
            for (int kk = 0; kk < 24; kk += 2) {
                loadx(xb, xr0, kb + kk + 1, rg);
                gemm_step(acc, xa, wc0, ((kb+kk)   ^ s0) << 2, ((kb+kk)   ^ s1) << 2);
                if (kk + 2 < 24) loadx(xa, xr0, kb + kk + 2, rg);
                gemm_step(acc, xb, wc0, ((kb+kk+1) ^ s0) << 2, ((kb+kk+1) ^ s1) << 2);
            }
        }

        // ---- 3. one-shot partial store (scalar, conflict-free) ----
        {
            float* myset = part_s + wid*SET_STRIDE;
            #pragma unroll
            for (int c = 0; c < 8; c++)
                #pragma unroll
                for (int r = 0; r < 4; r++)
                    myset[(4*c + cg)*33 + 4*rg + r] = sum2(acc[r][c]);
        }
        __syncthreads();

        const bool more = (t + 1 < SEQ);

        // ---- 4. emb prefetch for t+1: cp.async, waited at next step top ----
        if (more) {
            int id1 = __ldg(idrow + t + 1);
            const float4* erow = (const float4*)(emb + (size_t)id1 * EMBED);
            #pragma unroll
            for (int o = 0; o < 8; o++) {
                int k4 = (16 + o)*8 + dk;
                cp16_cg(sdst_s + ((k4 ^ ssw) << 4), erow + o*8 + dk);
            }
            CP_COMMIT();
        }

        // ---- 5. epilogue: sum 8 segments, gates, state update ----
        {
            float pf = bias_s[ 0 + ejj];
            float pi = bias_s[ 8 + ejj];
            float po = bias_s[16 + ejj];
            float pg = bias_s[24 + ejj];
            #pragma unroll
            for (int s = 0; s < 8; s++) {
                const float* sp = part_s + s*SET_STRIDE + eb;
                pf += sp[(4*ejj + 0)*33];
                pi += sp[(4*ejj + 1)*33];
                po += sp[(4*ejj + 2)*33];
                pg += sp[(4*ejj + 3)*33];
            }
            float f  = sigf(pf);
            float iv = sigf(pi);
            float o  = sigf(po);
            float gg = tanhfast(pg);
            cst = f*cst + iv*gg;
            float h = o * tanhfast(cst);
            mmax = fmaxf(mmax, h);
            g_h[(t + 1) & 1][(size_t)(b0 + eb)*HID + j0 + ejj] = h;
        }

        // ---- 6. distributed half barrier ----
        if (more) {
            __syncthreads();                  // all h stores issued (block HB)
            if (tid == 0)
                asm volatile("red.release.gpu.add.u64 [%0], %1;"
                             :: "l"(myctr), "l"(1ULL) : "memory");
            // warp-parallel poll: lanes 0..7 each watch one counter
            unsigned long long tgt =
                pbase + (unsigned long long)CTAS_PER_CTR * (t + 1);
            bool ok;
            do {
                unsigned long long cur = 0;
                if (lane < 8)
                    asm volatile("ld.acquire.gpu.u64 %0, [%1];"
                                 : "=l"(cur) : "l"(pollctr) : "memory");
                ok = __all_sync(0xffffffffu, (lane >= 8) || (cur >= tgt));
            } while (!ok);
            // no exit sync: each warp proceeds straight to its staging
        }
    }

    // ---- max-over-time out, then tiny FC on CTA 0 ----
    g_maxh[(size_t)(b0 + eb)*HID + j0 + ejj] = mmax;
    ticket_barrier();

    if (cta == 0) {
        int b  = tid >> 2;
        int ci = tid & 3;
        const float4* a4 = (const float4*)(g_maxh + (size_t)b * HID);
        const float4* w4 = (const float4*)(fcw + (size_t)ci * HID);
        float acc0 = fcb[ci];
        #pragma unroll 4
        for (int k = 0; k < HID/4; k++) {
            float4 a = __ldcg(a4 + k);
            float4 w = w4[k];
            acc0 += a.x*w.x + a.y*w.y + a.z*w.z + a.w*w.w;
        }
        out[b*NCLS + ci] = acc0;
    }
}

extern "C" void kernel_launch(void* const* d_in, const int* in_sizes, int n_in,
                              void* d_out, int out_size)
{
    const int*   ids = (const int*)  d_in[0];
    const float* emb = (const float*)d_in[1];
    const float* Wf  = (const float*)d_in[2];
    const float* bf  = (const float*)d_in[3];
    const float* Wi  = (const float*)d_in[4];
    const float* bi  = (const float*)d_in[5];
    const float* Wo  = (const float*)d_in[6];
    const float* bo  = (const float*)d_in[7];
    const float* Wc  = (const float*)d_in[8];
    const float* bc  = (const float*)d_in[9];
    const float* fcw = (const float*)d_in[10];
    const float* fcb = (const float*)d_in[11];
    float* out = (float*)d_out;

    cudaFuncSetAttribute(lstm_persistent,
                         cudaFuncAttributeMaxDynamicSharedMemorySize, SMEM_BYTES);
    lstm_persistent<<<NBLK, NTHR, SMEM_BYTES>>>(ids, emb, Wf, bf, Wi, bi,
                                                Wo, bo, Wc, bc, fcw, fcb, out);
}